// round 14
// baseline (speedup 1.0000x reference)
#include <cuda_runtime.h>
#include <cuda_fp16.h>
#include <stdint.h>

#define NUM_SEQS 4
#define SEQ_LEN  4096
#define NTOK     16384
#define HIDDEN   2048
#define CONV_DIM 2048
#define KSZ      4
#define BCX_COLS 6144
#define KDIM     2048

// ---------------- scratch (static device globals; allocation-free) ----------
__device__ __half g_bxh[(size_t)NTOK * CONV_DIM];    // gated input b*x (fp16)
__device__ __half g_ch[(size_t)NTOK * CONV_DIM];     // c gate (fp16)
__device__ __half g_ha[(size_t)NTOK * KDIM];         // fp16 hidden
__device__ __half g_w1p[(size_t)BCX_COLS * KDIM];    // fp16 w_in, rows permuted:
                                                     //  [0,4096): interleaved b,x ; [4096,6144): c
__device__ __half g_w2[(size_t)HIDDEN * KDIM];       // fp16 w_out
__device__ __half g_y[(size_t)NTOK * KDIM];          // fp16 y

// ---------------- ptx helpers (baseline ISA only) ----------------------------
__device__ __forceinline__ uint32_t smem_u32(const void* p) {
    uint32_t a;
    asm("{ .reg .u64 t; cvta.to.shared.u64 t, %1; cvt.u32.u64 %0, t; }" : "=r"(a) : "l"(p));
    return a;
}
__device__ __forceinline__ void cpasync16(uint32_t dst, const void* src) {
    asm volatile("cp.async.cg.shared.global [%0], [%1], 16;" :: "r"(dst), "l"(src));
}
__device__ __forceinline__ void cp_commit() { asm volatile("cp.async.commit_group;" ::: "memory"); }
__device__ __forceinline__ void cp_wait2()  { asm volatile("cp.async.wait_group 2;" ::: "memory"); }

#define LDSM4(r, addr)                                                      \
    asm volatile("ldmatrix.sync.aligned.m8n8.x4.shared.b16 {%0,%1,%2,%3}, [%4];" \
        : "=r"((r)[0]), "=r"((r)[1]), "=r"((r)[2]), "=r"((r)[3]) : "r"(addr))

#define MMAF16(acc, a, b0r, b1r)                                            \
    asm volatile("mma.sync.aligned.m16n8k16.row.col.f32.f16.f16.f32 "       \
        "{%0,%1,%2,%3}, {%4,%5,%6,%7}, {%8,%9}, {%0,%1,%2,%3};"             \
        : "+f"((acc)[0]), "+f"((acc)[1]), "+f"((acc)[2]), "+f"((acc)[3])    \
        : "r"((a)[0]), "r"((a)[1]), "r"((a)[2]), "r"((a)[3]),               \
          "r"(b0r), "r"(b1r))

__device__ __forceinline__ uint32_t swz64(uint32_t off) { return off ^ ((off >> 3) & 0x30); }

// ---------------- fp16 GEMM: C = A[M,K] @ B[N,K]^T --------------------------
// CTA 128x128, 4 warps (2x2), warp tile 64x64, BK=32 halves, 4-stage,
// double-buffered register fragments, 2 CTAs/SM.
// mode 0: plain fp32 C
// mode 1: FUSED in_proj: n0 < 4096 -> interleaved (b,x) -> bx fp16 (g_bxh)
//                        + fp32 states; n0 >= 4096 -> c plane fp16 (g_ch).
#define BM 128
#define BN 128
#define BKC 32
#define NC (KDIM / BKC)              // 64
#define OFF_A 0
#define OFF_B 8192
#define STAGE_BYTES 16384
#define GSMEM_TOTAL (4 * STAGE_BYTES)   // 64KB

__global__ __launch_bounds__(128, 2)
void gemm_f16(const __half* __restrict__ A, const __half* __restrict__ B,
              float* __restrict__ C, int ldC, int mode, float* __restrict__ states)
{
    extern __shared__ char smem[];
    const uint32_t sbase = smem_u32(smem);
    const int tid  = threadIdx.x;
    const int lane = tid & 31;
    const int wid  = tid >> 5;
    const int wm   = wid >> 1;
    const int wn   = wid & 1;
    const int m0 = blockIdx.y * BM;
    const int n0 = blockIdx.x * BN;

    const __half* gA = A + (size_t)m0 * KDIM;
    const __half* gB = B + (size_t)n0 * KDIM;

    uint32_t aRow[4], aXor[4];
#pragma unroll
    for (int mt = 0; mt < 4; mt++) {
        uint32_t r = wm * 64 + mt * 16 + (lane & 15);
        aRow[mt] = r * 64;
        aXor[mt] = (aRow[mt] >> 3) & 0x30;
    }
    const uint32_t aS = (lane >> 4);
    uint32_t bRow[4], bXor[4];
#pragma unroll
    for (int p = 0; p < 4; p++) {
        uint32_t r = wn * 64 + p * 16 + (lane & 7) + ((lane >> 4) << 3);
        bRow[p] = r * 64;
        bXor[p] = (bRow[p] >> 3) & 0x30;
    }
    const uint32_t bS = ((lane >> 3) & 1);

    float acc[4][8][4];
#pragma unroll
    for (int i = 0; i < 4; i++)
#pragma unroll
        for (int j = 0; j < 8; j++)
#pragma unroll
            for (int q = 0; q < 4; q++) acc[i][j][q] = 0.0f;

    auto load_chunk = [&](int c, int st) {
        const uint32_t stg = sbase + st * STAGE_BYTES;
        const int koff = c * BKC;
#pragma unroll
        for (int p = 0; p < 4; p++) {
            int u = p * 128 + tid;
            int r = u >> 2, s = u & 3;
            cpasync16(stg + OFF_A + swz64((uint32_t)(r * 64 + s * 16)),
                      gA + (size_t)r * KDIM + koff + s * 8);
        }
#pragma unroll
        for (int p = 0; p < 4; p++) {
            int u = p * 128 + tid;
            int r = u >> 2, s = u & 3;
            cpasync16(stg + OFF_B + swz64((uint32_t)(r * 64 + s * 16)),
                      gB + (size_t)r * KDIM + koff + s * 8);
        }
    };

    uint32_t af0[4][4], bf0[4][4], af1[4][4], bf1[4][4];

    auto ldsm_set = [&](uint32_t stg, int q, uint32_t af[4][4], uint32_t bf[4][4]) {
        const uint32_t s_a = (q * 2 + aS) * 16;
        const uint32_t s_b = (q * 2 + bS) * 16;
#pragma unroll
        for (int mt = 0; mt < 4; mt++)
            LDSM4(af[mt], stg + OFF_A + aRow[mt] + (s_a ^ aXor[mt]));
#pragma unroll
        for (int p = 0; p < 4; p++)
            LDSM4(bf[p], stg + OFF_B + bRow[p] + (s_b ^ bXor[p]));
    };

    auto mma_set = [&](uint32_t af[4][4], uint32_t bf[4][4]) {
#pragma unroll
        for (int mt = 0; mt < 4; mt++) {
#pragma unroll
            for (int nt = 0; nt < 8; nt++) {
                const int p = nt >> 1, bi = (nt & 1) * 2;
                MMAF16(acc[mt][nt], af[mt], bf[p][bi], bf[p][bi + 1]);
            }
        }
    };

    // prologue: stages 0,1,2
    load_chunk(0, 0); cp_commit();
    load_chunk(1, 1); cp_commit();
    load_chunk(2, 2); cp_commit();
    cp_wait2();
    __syncthreads();
    ldsm_set(sbase, 0, af0, bf0);

    for (int ch = 0; ch < NC; ch++) {
        const uint32_t stg = sbase + (ch & 3) * STAGE_BYTES;
        if (ch + 3 < NC) load_chunk(ch + 3, (ch + 3) & 3);
        cp_commit();

        ldsm_set(stg, 1, af1, bf1);
        mma_set(af0, bf0);
        mma_set(af1, bf1);

        cp_wait2();
        __syncthreads();
        if (ch + 1 < NC)
            ldsm_set(sbase + ((ch + 1) & 3) * STAGE_BYTES, 0, af0, bf0);
    }

    if (mode == 0) {
        const int rw = m0 + wm * 64 + (lane >> 2);
        const int cw = n0 + wn * 64 + (lane & 3) * 2;
#pragma unroll
        for (int mt = 0; mt < 4; mt++) {
#pragma unroll
            for (int nt = 0; nt < 8; nt++) {
                float* p0 = C + (size_t)(rw + mt * 16) * ldC + cw + nt * 8;
                float* p1 = C + (size_t)(rw + mt * 16 + 8) * ldC + cw + nt * 8;
                *(float2*)p0 = make_float2(acc[mt][nt][0], acc[mt][nt][1]);
                *(float2*)p1 = make_float2(acc[mt][nt][2], acc[mt][nt][3]);
            }
        }
    } else if (n0 < 4096) {
        // interleaved (b,x): acc cols (2i, 2i+1) = (b_i, x_i); bx col = i
        const int rw0  = m0 + wm * 64 + (lane >> 2);
        const int colb = (n0 >> 1) + wn * 32 + (lane & 3);
#pragma unroll
        for (int mt = 0; mt < 4; mt++) {
#pragma unroll
            for (int nt = 0; nt < 8; nt++) {
                int col = colb + nt * 4;
                int r0 = rw0 + mt * 16;
                int r1 = r0 + 8;
                float p0 = acc[mt][nt][0] * acc[mt][nt][1];
                float p1 = acc[mt][nt][2] * acc[mt][nt][3];
                g_bxh[(size_t)r0 * CONV_DIM + col] = __float2half_rn(p0);
                g_bxh[(size_t)r1 * CONV_DIM + col] = __float2half_rn(p1);
                int pos0 = r0 & (SEQ_LEN - 1);
                if (pos0 >= SEQ_LEN - (KSZ - 1))
                    states[((size_t)(r0 >> 12) * (KSZ - 1) + (pos0 - (SEQ_LEN - 3))) * CONV_DIM + col] = p0;
                int pos1 = r1 & (SEQ_LEN - 1);
                if (pos1 >= SEQ_LEN - (KSZ - 1))
                    states[((size_t)(r1 >> 12) * (KSZ - 1) + (pos1 - (SEQ_LEN - 3))) * CONV_DIM + col] = p1;
            }
        }
    } else {
        // c plane -> fp16 g_ch, col = n0 - 4096
        const int rw = m0 + wm * 64 + (lane >> 2);
        const int cw = (n0 - 4096) + wn * 64 + (lane & 3) * 2;
#pragma unroll
        for (int mt = 0; mt < 4; mt++) {
#pragma unroll
            for (int nt = 0; nt < 8; nt++) {
                __half2* p0 = (__half2*)&g_ch[(size_t)(rw + mt * 16) * CONV_DIM + cw + nt * 8];
                __half2* p1 = (__half2*)&g_ch[(size_t)(rw + mt * 16 + 8) * CONV_DIM + cw + nt * 8];
                *p0 = __floats2half2_rn(acc[mt][nt][0], acc[mt][nt][1]);
                *p1 = __floats2half2_rn(acc[mt][nt][2], acc[mt][nt][3]);
            }
        }
    }
}

// ---------------- fused fp32 -> fp16 converts (hidden | w_in permuted | w_out)
#define N4_HA (NTOK * KDIM / 4)
#define N4_W1 (BCX_COLS * KDIM / 4)
#define N4_W2 (HIDDEN * KDIM / 4)
#define N4_TOTAL (N4_HA + N4_W1 + N4_W2)

__global__ __launch_bounds__(256)
void cvt_all_kernel(const float* __restrict__ hidden, const float* __restrict__ w_in,
                    const float* __restrict__ w_out)
{
    int base = blockIdx.x * blockDim.x * 2 + threadIdx.x;
#pragma unroll
    for (int rep = 0; rep < 2; rep++) {
        int i = base + rep * 256;
        if (i >= N4_TOTAL) return;
        if (i < N4_HA) {
            float4 v = ((const float4*)hidden)[i];
            ((__half2*)g_ha)[i * 2 + 0] = __floats2half2_rn(v.x, v.y);
            ((__half2*)g_ha)[i * 2 + 1] = __floats2half2_rn(v.z, v.w);
        } else if (i < N4_HA + N4_W1) {
            int j = i - N4_HA;
            int r = (j * 4) / KDIM, k = (j * 4) % KDIM;
            int sr = (r < 4096) ? ((r >> 1) + ((r & 1) ? 4096 : 0)) : (r - 2048);
            float4 v = *(const float4*)(w_in + (size_t)sr * KDIM + k);
            ((__half2*)g_w1p)[j * 2 + 0] = __floats2half2_rn(v.x, v.y);
            ((__half2*)g_w1p)[j * 2 + 1] = __floats2half2_rn(v.z, v.w);
        } else {
            int j = i - N4_HA - N4_W1;
            float4 v = ((const float4*)w_out)[j];
            ((__half2*)g_w2)[j * 2 + 0] = __floats2half2_rn(v.x, v.y);
            ((__half2*)g_w2)[j * 2 + 1] = __floats2half2_rn(v.z, v.w);
        }
    }
}

// ---------------- causal conv + BCx gate, 2 channels/thread, 16-token strips -
#define TPER 16
#define DPAIRS (CONV_DIM / 2)   // 1024

__global__ __launch_bounds__(256)
void conv_gate_kernel(const float* __restrict__ cw)
{
    int dp = blockIdx.x * blockDim.x + threadIdx.x;  // channel pair 0..1023
    int t0 = blockIdx.y * TPER;
    int pos0 = t0 & (SEQ_LEN - 1);

    const __half2* bxp = (const __half2*)g_bxh;
    const __half2* chp = (const __half2*)g_ch;
    __half2* yp = (__half2*)g_y;

    float4 wa = *(const float4*)(cw + dp * 8);       // channel 2*dp
    float4 wb = *(const float4*)(cw + dp * 8 + 4);   // channel 2*dp+1

    float2 h0 = {0.f, 0.f}, h1 = {0.f, 0.f}, h2 = {0.f, 0.f};
    if (pos0 >= 3) h0 = __half22float2(bxp[(size_t)(t0 - 3) * DPAIRS + dp]);
    if (pos0 >= 2) h1 = __half22float2(bxp[(size_t)(t0 - 2) * DPAIRS + dp]);
    if (pos0 >= 1) h2 = __half22float2(bxp[(size_t)(t0 - 1) * DPAIRS + dp]);

#pragma unroll
    for (int i = 0; i < TPER; i++) {
        size_t idx = (size_t)(t0 + i) * DPAIRS + dp;
        float2 bx = __half22float2(bxp[idx]);
        float cx = fmaf(wa.x, h0.x, fmaf(wa.y, h1.x, fmaf(wa.z, h2.x, wa.w * bx.x)));
        float cy = fmaf(wb.x, h0.y, fmaf(wb.y, h1.y, fmaf(wb.z, h2.y, wb.w * bx.y)));
        float2 c = __half22float2(chp[idx]);
        yp[idx] = __floats2half2_rn(c.x * cx, c.y * cy);
        h0 = h1; h1 = h2; h2 = bx;
    }
}

// ---------------- launch -----------------------------------------------------
extern "C" void kernel_launch(void* const* d_in, const int* in_sizes, int n_in,
                              void* d_out, int out_size)
{
    const float* hidden = (const float*)d_in[0];
    const float* w_in   = (const float*)d_in[1];
    const float* convw  = (const float*)d_in[2];
    const float* w_out  = (const float*)d_in[3];
    float* out = (float*)d_out;
    float* states = out + (size_t)NTOK * HIDDEN;

    __half *ha, *w1p, *w2, *y;
    cudaGetSymbolAddress((void**)&ha,  g_ha);
    cudaGetSymbolAddress((void**)&w1p, g_w1p);
    cudaGetSymbolAddress((void**)&w2,  g_w2);
    cudaGetSymbolAddress((void**)&y,   g_y);

    cudaFuncSetAttribute(gemm_f16, cudaFuncAttributeMaxDynamicSharedMemorySize, GSMEM_TOTAL);

    // 0) fused fp16 conversions
    cvt_all_kernel<<<(N4_TOTAL + 511) / 512, 256>>>(hidden, w_in, w_out);

    // 1) FUSED in_proj GEMM: bx=b*x fp16 (+fp32 states) AND c-plane fp16
    gemm_f16<<<dim3(BCX_COLS / BN, NTOK / BM), 128, GSMEM_TOTAL>>>(
        ha, w1p, nullptr, CONV_DIM, 1, states);

    // 2) conv + BCx gate -> y (fp16), 2 channels/thread, 16-token strips
    conv_gate_kernel<<<dim3(DPAIRS / 256, NTOK / TPER), 256>>>(convw);

    // 3) GEMM2: out = y @ w_out^T
    gemm_f16<<<dim3(HIDDEN / BN, NTOK / BM), 128, GSMEM_TOTAL>>>(
        y, w2, out, HIDDEN, 0, nullptr);
}

// round 15
// speedup vs baseline: 1.0021x; 1.0021x over previous
#include <cuda_runtime.h>
#include <cuda_fp16.h>
#include <stdint.h>

#define NUM_SEQS 4
#define SEQ_LEN  4096
#define NTOK     16384
#define HIDDEN   2048
#define CONV_DIM 2048
#define KSZ      4
#define BCX_COLS 6144
#define KDIM     2048

// ---------------- scratch (static device globals; allocation-free) ----------
__device__ __half g_bxh[(size_t)NTOK * CONV_DIM];    // gated input b*x (fp16)
__device__ __half g_ch[(size_t)NTOK * CONV_DIM];     // c gate (fp16)
__device__ __half g_ha[(size_t)NTOK * KDIM];         // fp16 hidden
__device__ __half g_w1p[(size_t)BCX_COLS * KDIM];    // fp16 w_in, rows permuted:
                                                     //  [0,4096): interleaved b,x ; [4096,6144): c
__device__ __half g_w2[(size_t)HIDDEN * KDIM];       // fp16 w_out
__device__ __half g_y[(size_t)NTOK * KDIM];          // fp16 y

// ---------------- ptx helpers (baseline ISA only) ----------------------------
__device__ __forceinline__ uint32_t smem_u32(const void* p) {
    uint32_t a;
    asm("{ .reg .u64 t; cvta.to.shared.u64 t, %1; cvt.u32.u64 %0, t; }" : "=r"(a) : "l"(p));
    return a;
}
__device__ __forceinline__ void cpasync16(uint32_t dst, const void* src) {
    asm volatile("cp.async.cg.shared.global [%0], [%1], 16;" :: "r"(dst), "l"(src));
}
__device__ __forceinline__ void cp_commit() { asm volatile("cp.async.commit_group;" ::: "memory"); }
__device__ __forceinline__ void cp_wait2()  { asm volatile("cp.async.wait_group 2;" ::: "memory"); }

#define LDSM4(r, addr)                                                      \
    asm volatile("ldmatrix.sync.aligned.m8n8.x4.shared.b16 {%0,%1,%2,%3}, [%4];" \
        : "=r"((r)[0]), "=r"((r)[1]), "=r"((r)[2]), "=r"((r)[3]) : "r"(addr))

#define MMAF16(acc, a, b0r, b1r)                                            \
    asm volatile("mma.sync.aligned.m16n8k16.row.col.f32.f16.f16.f32 "       \
        "{%0,%1,%2,%3}, {%4,%5,%6,%7}, {%8,%9}, {%0,%1,%2,%3};"             \
        : "+f"((acc)[0]), "+f"((acc)[1]), "+f"((acc)[2]), "+f"((acc)[3])    \
        : "r"((a)[0]), "r"((a)[1]), "r"((a)[2]), "r"((a)[3]),               \
          "r"(b0r), "r"(b1r))

__device__ __forceinline__ uint32_t swz64(uint32_t off) { return off ^ ((off >> 3) & 0x30); }

// ---------------- fp16 GEMM: C = A[M,K] @ B[N,K]^T --------------------------
// CTA 128x128, 4 warps (2x2), warp tile 64x64, BK=32 halves, 4-stage,
// double-buffered register fragments, 2 CTAs/SM.
// mode 0: plain fp32 C
// mode 1: FUSED in_proj: n0 < 4096 -> interleaved (b,x) -> bx fp16 (g_bxh)
//                        + fp32 states; n0 >= 4096 -> c plane fp16 (g_ch).
#define BM 128
#define BN 128
#define BKC 32
#define NC (KDIM / BKC)              // 64
#define OFF_A 0
#define OFF_B 8192
#define STAGE_BYTES 16384
#define GSMEM_TOTAL (4 * STAGE_BYTES)   // 64KB

__global__ __launch_bounds__(128, 2)
void gemm_f16(const __half* __restrict__ A, const __half* __restrict__ B,
              float* __restrict__ C, int ldC, int mode, float* __restrict__ states)
{
    extern __shared__ char smem[];
    const uint32_t sbase = smem_u32(smem);
    const int tid  = threadIdx.x;
    const int lane = tid & 31;
    const int wid  = tid >> 5;
    const int wm   = wid >> 1;
    const int wn   = wid & 1;
    const int m0 = blockIdx.y * BM;
    const int n0 = blockIdx.x * BN;

    const __half* gA = A + (size_t)m0 * KDIM;
    const __half* gB = B + (size_t)n0 * KDIM;

    uint32_t aRow[4], aXor[4];
#pragma unroll
    for (int mt = 0; mt < 4; mt++) {
        uint32_t r = wm * 64 + mt * 16 + (lane & 15);
        aRow[mt] = r * 64;
        aXor[mt] = (aRow[mt] >> 3) & 0x30;
    }
    const uint32_t aS = (lane >> 4);
    uint32_t bRow[4], bXor[4];
#pragma unroll
    for (int p = 0; p < 4; p++) {
        uint32_t r = wn * 64 + p * 16 + (lane & 7) + ((lane >> 4) << 3);
        bRow[p] = r * 64;
        bXor[p] = (bRow[p] >> 3) & 0x30;
    }
    const uint32_t bS = ((lane >> 3) & 1);

    float acc[4][8][4];
#pragma unroll
    for (int i = 0; i < 4; i++)
#pragma unroll
        for (int j = 0; j < 8; j++)
#pragma unroll
            for (int q = 0; q < 4; q++) acc[i][j][q] = 0.0f;

    auto load_chunk = [&](int c, int st) {
        const uint32_t stg = sbase + st * STAGE_BYTES;
        const int koff = c * BKC;
#pragma unroll
        for (int p = 0; p < 4; p++) {
            int u = p * 128 + tid;
            int r = u >> 2, s = u & 3;
            cpasync16(stg + OFF_A + swz64((uint32_t)(r * 64 + s * 16)),
                      gA + (size_t)r * KDIM + koff + s * 8);
        }
#pragma unroll
        for (int p = 0; p < 4; p++) {
            int u = p * 128 + tid;
            int r = u >> 2, s = u & 3;
            cpasync16(stg + OFF_B + swz64((uint32_t)(r * 64 + s * 16)),
                      gB + (size_t)r * KDIM + koff + s * 8);
        }
    };

    uint32_t af0[4][4], bf0[4][4], af1[4][4], bf1[4][4];

    auto ldsm_set = [&](uint32_t stg, int q, uint32_t af[4][4], uint32_t bf[4][4]) {
        const uint32_t s_a = (q * 2 + aS) * 16;
        const uint32_t s_b = (q * 2 + bS) * 16;
#pragma unroll
        for (int mt = 0; mt < 4; mt++)
            LDSM4(af[mt], stg + OFF_A + aRow[mt] + (s_a ^ aXor[mt]));
#pragma unroll
        for (int p = 0; p < 4; p++)
            LDSM4(bf[p], stg + OFF_B + bRow[p] + (s_b ^ bXor[p]));
    };

    auto mma_set = [&](uint32_t af[4][4], uint32_t bf[4][4]) {
#pragma unroll
        for (int mt = 0; mt < 4; mt++) {
#pragma unroll
            for (int nt = 0; nt < 8; nt++) {
                const int p = nt >> 1, bi = (nt & 1) * 2;
                MMAF16(acc[mt][nt], af[mt], bf[p][bi], bf[p][bi + 1]);
            }
        }
    };

    // prologue: stages 0,1,2
    load_chunk(0, 0); cp_commit();
    load_chunk(1, 1); cp_commit();
    load_chunk(2, 2); cp_commit();
    cp_wait2();
    __syncthreads();
    ldsm_set(sbase, 0, af0, bf0);

    for (int ch = 0; ch < NC; ch++) {
        const uint32_t stg = sbase + (ch & 3) * STAGE_BYTES;
        if (ch + 3 < NC) load_chunk(ch + 3, (ch + 3) & 3);
        cp_commit();

        ldsm_set(stg, 1, af1, bf1);
        mma_set(af0, bf0);
        mma_set(af1, bf1);

        cp_wait2();
        __syncthreads();
        if (ch + 1 < NC)
            ldsm_set(sbase + ((ch + 1) & 3) * STAGE_BYTES, 0, af0, bf0);
    }

    if (mode == 0) {
        const int rw = m0 + wm * 64 + (lane >> 2);
        const int cw = n0 + wn * 64 + (lane & 3) * 2;
#pragma unroll
        for (int mt = 0; mt < 4; mt++) {
#pragma unroll
            for (int nt = 0; nt < 8; nt++) {
                float* p0 = C + (size_t)(rw + mt * 16) * ldC + cw + nt * 8;
                float* p1 = C + (size_t)(rw + mt * 16 + 8) * ldC + cw + nt * 8;
                *(float2*)p0 = make_float2(acc[mt][nt][0], acc[mt][nt][1]);
                *(float2*)p1 = make_float2(acc[mt][nt][2], acc[mt][nt][3]);
            }
        }
    } else if (n0 < 4096) {
        // interleaved (b,x): acc cols (2i, 2i+1) = (b_i, x_i); bx col = i
        const int rw0  = m0 + wm * 64 + (lane >> 2);
        const int colb = (n0 >> 1) + wn * 32 + (lane & 3);
#pragma unroll
        for (int mt = 0; mt < 4; mt++) {
#pragma unroll
            for (int nt = 0; nt < 8; nt++) {
                int col = colb + nt * 4;
                int r0 = rw0 + mt * 16;
                int r1 = r0 + 8;
                float p0 = acc[mt][nt][0] * acc[mt][nt][1];
                float p1 = acc[mt][nt][2] * acc[mt][nt][3];
                g_bxh[(size_t)r0 * CONV_DIM + col] = __float2half_rn(p0);
                g_bxh[(size_t)r1 * CONV_DIM + col] = __float2half_rn(p1);
                int pos0 = r0 & (SEQ_LEN - 1);
                if (pos0 >= SEQ_LEN - (KSZ - 1))
                    states[((size_t)(r0 >> 12) * (KSZ - 1) + (pos0 - (SEQ_LEN - 3))) * CONV_DIM + col] = p0;
                int pos1 = r1 & (SEQ_LEN - 1);
                if (pos1 >= SEQ_LEN - (KSZ - 1))
                    states[((size_t)(r1 >> 12) * (KSZ - 1) + (pos1 - (SEQ_LEN - 3))) * CONV_DIM + col] = p1;
            }
        }
    } else {
        // c plane -> fp16 g_ch, col = n0 - 4096
        const int rw = m0 + wm * 64 + (lane >> 2);
        const int cw = (n0 - 4096) + wn * 64 + (lane & 3) * 2;
#pragma unroll
        for (int mt = 0; mt < 4; mt++) {
#pragma unroll
            for (int nt = 0; nt < 8; nt++) {
                __half2* p0 = (__half2*)&g_ch[(size_t)(rw + mt * 16) * CONV_DIM + cw + nt * 8];
                __half2* p1 = (__half2*)&g_ch[(size_t)(rw + mt * 16 + 8) * CONV_DIM + cw + nt * 8];
                *p0 = __floats2half2_rn(acc[mt][nt][0], acc[mt][nt][1]);
                *p1 = __floats2half2_rn(acc[mt][nt][2], acc[mt][nt][3]);
            }
        }
    }
}

// ---------------- fused fp32 -> fp16 converts (hidden | w_in permuted | w_out)
#define N4_HA (NTOK * KDIM / 4)
#define N4_W1 (BCX_COLS * KDIM / 4)
#define N4_W2 (HIDDEN * KDIM / 4)

__global__ __launch_bounds__(256)
void cvt_all_kernel(const float* __restrict__ hidden, const float* __restrict__ w_in,
                    const float* __restrict__ w_out)
{
    int i = blockIdx.x * blockDim.x + threadIdx.x;
    const float* src;
    __half* dst;
    int j;
    if (i < N4_HA) {
        j = i; src = hidden; dst = g_ha;
    } else if (i < N4_HA + N4_W1) {
        j = i - N4_HA;
        int r = (j * 4) / KDIM, k = (j * 4) % KDIM;
        int sr = (r < 4096) ? ((r >> 1) + ((r & 1) ? 4096 : 0)) : (r - 2048);
        float4 v = *(const float4*)(w_in + (size_t)sr * KDIM + k);
        ((__half2*)g_w1p)[j * 2 + 0] = __floats2half2_rn(v.x, v.y);
        ((__half2*)g_w1p)[j * 2 + 1] = __floats2half2_rn(v.z, v.w);
        return;
    } else if (i < N4_HA + N4_W1 + N4_W2) {
        j = i - N4_HA - N4_W1; src = w_out; dst = g_w2;
    } else return;
    float4 v = ((const float4*)src)[j];
    ((__half2*)dst)[j * 2 + 0] = __floats2half2_rn(v.x, v.y);
    ((__half2*)dst)[j * 2 + 1] = __floats2half2_rn(v.z, v.w);
}

// ---------------- causal conv + BCx gate, 4 channels/thread, 8-token strips --
#define TPER 8
#define DQUADS (CONV_DIM / 4)   // 512

__device__ __forceinline__ float2 h2f(uint32_t u) {
    return __half22float2(*(__half2*)&u);
}

__global__ __launch_bounds__(256)
void conv_gate_kernel(const float* __restrict__ cw)
{
    int dq = blockIdx.x * blockDim.x + threadIdx.x;  // channel quad 0..511
    int t0 = blockIdx.y * TPER;
    int pos0 = t0 & (SEQ_LEN - 1);

    const uint4* bxp = (const uint4*)g_bxh;          // 4 halves per uint4... 8 halves = uint4
    // NOTE: uint4 = 16B = 8 halves; we want 4 halves (8B) per thread -> use uint2.
    const uint2* bx2 = (const uint2*)g_bxh;
    const uint2* c2  = (const uint2*)g_ch;
    uint2* y2 = (uint2*)g_y;
    (void)bxp;

    // weights for channels 4*dq .. 4*dq+3
    float4 w0v = *(const float4*)(cw + dq * 16);
    float4 w1v = *(const float4*)(cw + dq * 16 + 4);
    float4 w2v = *(const float4*)(cw + dq * 16 + 8);
    float4 w3v = *(const float4*)(cw + dq * 16 + 12);

    float4 h0 = {0,0,0,0}, h1 = {0,0,0,0}, h2v = {0,0,0,0};
    auto loadbx = [&](int t) -> float4 {
        uint2 u = bx2[(size_t)t * DQUADS + dq];
        float2 lo = h2f(u.x), hi = h2f(u.y);
        return make_float4(lo.x, lo.y, hi.x, hi.y);
    };
    if (pos0 >= 3) h0 = loadbx(t0 - 3);
    if (pos0 >= 2) h1 = loadbx(t0 - 2);
    if (pos0 >= 1) h2v = loadbx(t0 - 1);

#pragma unroll
    for (int i = 0; i < TPER; i++) {
        size_t idx = (size_t)(t0 + i) * DQUADS + dq;
        uint2 ub = bx2[idx];
        float2 blo = h2f(ub.x), bhi = h2f(ub.y);
        float4 bx = make_float4(blo.x, blo.y, bhi.x, bhi.y);

        float r0 = fmaf(w0v.x, h0.x, fmaf(w0v.y, h1.x, fmaf(w0v.z, h2v.x, w0v.w * bx.x)));
        float r1 = fmaf(w1v.x, h0.y, fmaf(w1v.y, h1.y, fmaf(w1v.z, h2v.y, w1v.w * bx.y)));
        float r2 = fmaf(w2v.x, h0.z, fmaf(w2v.y, h1.z, fmaf(w2v.z, h2v.z, w2v.w * bx.z)));
        float r3 = fmaf(w3v.x, h0.w, fmaf(w3v.y, h1.w, fmaf(w3v.z, h2v.w, w3v.w * bx.w)));

        uint2 uc = c2[idx];
        float2 clo = h2f(uc.x), chi = h2f(uc.y);

        __half2 ylo = __floats2half2_rn(clo.x * r0, clo.y * r1);
        __half2 yhi = __floats2half2_rn(chi.x * r2, chi.y * r3);
        uint2 uy;
        uy.x = *(uint32_t*)&ylo;
        uy.y = *(uint32_t*)&yhi;
        y2[idx] = uy;

        h0 = h1; h1 = h2v; h2v = bx;
    }
}

// ---------------- launch -----------------------------------------------------
extern "C" void kernel_launch(void* const* d_in, const int* in_sizes, int n_in,
                              void* d_out, int out_size)
{
    const float* hidden = (const float*)d_in[0];
    const float* w_in   = (const float*)d_in[1];
    const float* convw  = (const float*)d_in[2];
    const float* w_out  = (const float*)d_in[3];
    float* out = (float*)d_out;
    float* states = out + (size_t)NTOK * HIDDEN;

    __half *ha, *w1p, *w2, *y;
    cudaGetSymbolAddress((void**)&ha,  g_ha);
    cudaGetSymbolAddress((void**)&w1p, g_w1p);
    cudaGetSymbolAddress((void**)&w2,  g_w2);
    cudaGetSymbolAddress((void**)&y,   g_y);

    cudaFuncSetAttribute(gemm_f16, cudaFuncAttributeMaxDynamicSharedMemorySize, GSMEM_TOTAL);

    // 0) fused fp16 conversions
    {
        int total = N4_HA + N4_W1 + N4_W2;
        cvt_all_kernel<<<(total + 255) / 256, 256>>>(hidden, w_in, w_out);
    }

    // 1) FUSED in_proj GEMM: bx=b*x fp16 (+fp32 states) AND c-plane fp16
    gemm_f16<<<dim3(BCX_COLS / BN, NTOK / BM), 128, GSMEM_TOTAL>>>(
        ha, w1p, nullptr, CONV_DIM, 1, states);

    // 2) conv + BCx gate -> y (fp16), 4 channels/thread, 8-token strips
    conv_gate_kernel<<<dim3(DQUADS / 256, NTOK / TPER), 256>>>(convw);

    // 3) GEMM2: out = y @ w_out^T
    gemm_f16<<<dim3(HIDDEN / BN, NTOK / BM), 128, GSMEM_TOTAL>>>(
        y, w2, out, HIDDEN, 0, nullptr);
}

// round 16
// speedup vs baseline: 1.0028x; 1.0008x over previous
#include <cuda_runtime.h>
#include <cuda_fp16.h>
#include <stdint.h>

#define NUM_SEQS 4
#define SEQ_LEN  4096
#define NTOK     16384
#define HIDDEN   2048
#define CONV_DIM 2048
#define KSZ      4
#define BCX_COLS 6144
#define KDIM     2048

// ---------------- scratch (static device globals; allocation-free) ----------
__device__ __half g_bxh[(size_t)NTOK * CONV_DIM];    // gated input b*x (fp16)
__device__ __half g_ch[(size_t)NTOK * CONV_DIM];     // c gate (fp16)
__device__ __half g_ha[(size_t)NTOK * KDIM];         // fp16 hidden
__device__ __half g_w1p[(size_t)BCX_COLS * KDIM];    // fp16 w_in, rows permuted:
                                                     //  [0,4096): interleaved b,x ; [4096,6144): c
__device__ __half g_w2[(size_t)HIDDEN * KDIM];       // fp16 w_out
__device__ __half g_y[(size_t)NTOK * KDIM];          // fp16 y

// ---------------- ptx helpers (baseline ISA only) ----------------------------
__device__ __forceinline__ uint32_t smem_u32(const void* p) {
    uint32_t a;
    asm("{ .reg .u64 t; cvta.to.shared.u64 t, %1; cvt.u32.u64 %0, t; }" : "=r"(a) : "l"(p));
    return a;
}
__device__ __forceinline__ void cpasync16(uint32_t dst, const void* src) {
    asm volatile("cp.async.cg.shared.global [%0], [%1], 16;" :: "r"(dst), "l"(src));
}
__device__ __forceinline__ void cp_commit() { asm volatile("cp.async.commit_group;" ::: "memory"); }
__device__ __forceinline__ void cp_wait2()  { asm volatile("cp.async.wait_group 2;" ::: "memory"); }

#define LDSM4(r, addr)                                                      \
    asm volatile("ldmatrix.sync.aligned.m8n8.x4.shared.b16 {%0,%1,%2,%3}, [%4];" \
        : "=r"((r)[0]), "=r"((r)[1]), "=r"((r)[2]), "=r"((r)[3]) : "r"(addr))

#define MMAF16(acc, a, b0r, b1r)                                            \
    asm volatile("mma.sync.aligned.m16n8k16.row.col.f32.f16.f16.f32 "       \
        "{%0,%1,%2,%3}, {%4,%5,%6,%7}, {%8,%9}, {%0,%1,%2,%3};"             \
        : "+f"((acc)[0]), "+f"((acc)[1]), "+f"((acc)[2]), "+f"((acc)[3])    \
        : "r"((a)[0]), "r"((a)[1]), "r"((a)[2]), "r"((a)[3]),               \
          "r"(b0r), "r"(b1r))

__device__ __forceinline__ uint32_t swz64(uint32_t off) { return off ^ ((off >> 3) & 0x30); }

// ---------------- fp16 GEMM: C = A[M,K] @ B[N,K]^T --------------------------
// CTA 128x128, 4 warps (2x2), warp tile 64x64, BK=32 halves, 4-stage,
// double-buffered register fragments, 2 CTAs/SM.
// mode 0: plain fp32 C
// mode 1: FUSED in_proj: n0 < 4096 -> interleaved (b,x) -> bx fp16 (g_bxh)
//                        + fp32 states; n0 >= 4096 -> c plane fp16 (g_ch).
#define BM 128
#define BN 128
#define BKC 32
#define NC (KDIM / BKC)              // 64
#define OFF_A 0
#define OFF_B 8192
#define STAGE_BYTES 16384
#define GSMEM_TOTAL (4 * STAGE_BYTES)   // 64KB

__global__ __launch_bounds__(128, 2)
void gemm_f16(const __half* __restrict__ A, const __half* __restrict__ B,
              float* __restrict__ C, int ldC, int mode, float* __restrict__ states)
{
    extern __shared__ char smem[];
    const uint32_t sbase = smem_u32(smem);
    const int tid  = threadIdx.x;
    const int lane = tid & 31;
    const int wid  = tid >> 5;
    const int wm   = wid >> 1;
    const int wn   = wid & 1;
    const int m0 = blockIdx.y * BM;
    const int n0 = blockIdx.x * BN;

    const __half* gA = A + (size_t)m0 * KDIM;
    const __half* gB = B + (size_t)n0 * KDIM;

    uint32_t aRow[4], aXor[4];
#pragma unroll
    for (int mt = 0; mt < 4; mt++) {
        uint32_t r = wm * 64 + mt * 16 + (lane & 15);
        aRow[mt] = r * 64;
        aXor[mt] = (aRow[mt] >> 3) & 0x30;
    }
    const uint32_t aS = (lane >> 4);
    uint32_t bRow[4], bXor[4];
#pragma unroll
    for (int p = 0; p < 4; p++) {
        uint32_t r = wn * 64 + p * 16 + (lane & 7) + ((lane >> 4) << 3);
        bRow[p] = r * 64;
        bXor[p] = (bRow[p] >> 3) & 0x30;
    }
    const uint32_t bS = ((lane >> 3) & 1);

    float acc[4][8][4];
#pragma unroll
    for (int i = 0; i < 4; i++)
#pragma unroll
        for (int j = 0; j < 8; j++)
#pragma unroll
            for (int q = 0; q < 4; q++) acc[i][j][q] = 0.0f;

    auto load_chunk = [&](int c, int st) {
        const uint32_t stg = sbase + st * STAGE_BYTES;
        const int koff = c * BKC;
#pragma unroll
        for (int p = 0; p < 4; p++) {
            int u = p * 128 + tid;
            int r = u >> 2, s = u & 3;
            cpasync16(stg + OFF_A + swz64((uint32_t)(r * 64 + s * 16)),
                      gA + (size_t)r * KDIM + koff + s * 8);
        }
#pragma unroll
        for (int p = 0; p < 4; p++) {
            int u = p * 128 + tid;
            int r = u >> 2, s = u & 3;
            cpasync16(stg + OFF_B + swz64((uint32_t)(r * 64 + s * 16)),
                      gB + (size_t)r * KDIM + koff + s * 8);
        }
    };

    uint32_t af0[4][4], bf0[4][4], af1[4][4], bf1[4][4];

    auto ldsm_set = [&](uint32_t stg, int q, uint32_t af[4][4], uint32_t bf[4][4]) {
        const uint32_t s_a = (q * 2 + aS) * 16;
        const uint32_t s_b = (q * 2 + bS) * 16;
#pragma unroll
        for (int mt = 0; mt < 4; mt++)
            LDSM4(af[mt], stg + OFF_A + aRow[mt] + (s_a ^ aXor[mt]));
#pragma unroll
        for (int p = 0; p < 4; p++)
            LDSM4(bf[p], stg + OFF_B + bRow[p] + (s_b ^ bXor[p]));
    };

    auto mma_set = [&](uint32_t af[4][4], uint32_t bf[4][4]) {
#pragma unroll
        for (int mt = 0; mt < 4; mt++) {
#pragma unroll
            for (int nt = 0; nt < 8; nt++) {
                const int p = nt >> 1, bi = (nt & 1) * 2;
                MMAF16(acc[mt][nt], af[mt], bf[p][bi], bf[p][bi + 1]);
            }
        }
    };

    // prologue: stages 0,1,2
    load_chunk(0, 0); cp_commit();
    load_chunk(1, 1); cp_commit();
    load_chunk(2, 2); cp_commit();
    cp_wait2();
    __syncthreads();
    ldsm_set(sbase, 0, af0, bf0);

    for (int ch = 0; ch < NC; ch++) {
        const uint32_t stg = sbase + (ch & 3) * STAGE_BYTES;
        if (ch + 3 < NC) load_chunk(ch + 3, (ch + 3) & 3);
        cp_commit();

        ldsm_set(stg, 1, af1, bf1);
        mma_set(af0, bf0);
        mma_set(af1, bf1);

        cp_wait2();
        __syncthreads();
        if (ch + 1 < NC)
            ldsm_set(sbase + ((ch + 1) & 3) * STAGE_BYTES, 0, af0, bf0);
    }

    if (mode == 0) {
        const int rw = m0 + wm * 64 + (lane >> 2);
        const int cw = n0 + wn * 64 + (lane & 3) * 2;
#pragma unroll
        for (int mt = 0; mt < 4; mt++) {
#pragma unroll
            for (int nt = 0; nt < 8; nt++) {
                float* p0 = C + (size_t)(rw + mt * 16) * ldC + cw + nt * 8;
                float* p1 = C + (size_t)(rw + mt * 16 + 8) * ldC + cw + nt * 8;
                *(float2*)p0 = make_float2(acc[mt][nt][0], acc[mt][nt][1]);
                *(float2*)p1 = make_float2(acc[mt][nt][2], acc[mt][nt][3]);
            }
        }
    } else if (n0 < 4096) {
        // interleaved (b,x): acc cols (2i, 2i+1) = (b_i, x_i); bx col = i
        const int rw0  = m0 + wm * 64 + (lane >> 2);
        const int colb = (n0 >> 1) + wn * 32 + (lane & 3);
#pragma unroll
        for (int mt = 0; mt < 4; mt++) {
#pragma unroll
            for (int nt = 0; nt < 8; nt++) {
                int col = colb + nt * 4;
                int r0 = rw0 + mt * 16;
                int r1 = r0 + 8;
                float p0 = acc[mt][nt][0] * acc[mt][nt][1];
                float p1 = acc[mt][nt][2] * acc[mt][nt][3];
                g_bxh[(size_t)r0 * CONV_DIM + col] = __float2half_rn(p0);
                g_bxh[(size_t)r1 * CONV_DIM + col] = __float2half_rn(p1);
                int pos0 = r0 & (SEQ_LEN - 1);
                if (pos0 >= SEQ_LEN - (KSZ - 1))
                    states[((size_t)(r0 >> 12) * (KSZ - 1) + (pos0 - (SEQ_LEN - 3))) * CONV_DIM + col] = p0;
                int pos1 = r1 & (SEQ_LEN - 1);
                if (pos1 >= SEQ_LEN - (KSZ - 1))
                    states[((size_t)(r1 >> 12) * (KSZ - 1) + (pos1 - (SEQ_LEN - 3))) * CONV_DIM + col] = p1;
            }
        }
    } else {
        // c plane -> fp16 g_ch, col = n0 - 4096
        const int rw = m0 + wm * 64 + (lane >> 2);
        const int cw = (n0 - 4096) + wn * 64 + (lane & 3) * 2;
#pragma unroll
        for (int mt = 0; mt < 4; mt++) {
#pragma unroll
            for (int nt = 0; nt < 8; nt++) {
                __half2* p0 = (__half2*)&g_ch[(size_t)(rw + mt * 16) * CONV_DIM + cw + nt * 8];
                __half2* p1 = (__half2*)&g_ch[(size_t)(rw + mt * 16 + 8) * CONV_DIM + cw + nt * 8];
                *p0 = __floats2half2_rn(acc[mt][nt][0], acc[mt][nt][1]);
                *p1 = __floats2half2_rn(acc[mt][nt][2], acc[mt][nt][3]);
            }
        }
    }
}

// ---------------- fused fp32 -> fp16 converts (hidden | w_in permuted | w_out)
#define N4_HA (NTOK * KDIM / 4)
#define N4_W1 (BCX_COLS * KDIM / 4)
#define N4_W2 (HIDDEN * KDIM / 4)

__global__ __launch_bounds__(256)
void cvt_all_kernel(const float* __restrict__ hidden, const float* __restrict__ w_in,
                    const float* __restrict__ w_out)
{
    int i = blockIdx.x * blockDim.x + threadIdx.x;
    const float* src;
    __half* dst;
    int j;
    if (i < N4_HA) {
        j = i; src = hidden; dst = g_ha;
    } else if (i < N4_HA + N4_W1) {
        j = i - N4_HA;
        int r = (j * 4) / KDIM, k = (j * 4) % KDIM;
        int sr = (r < 4096) ? ((r >> 1) + ((r & 1) ? 4096 : 0)) : (r - 2048);
        float4 v = *(const float4*)(w_in + (size_t)sr * KDIM + k);
        ((__half2*)g_w1p)[j * 2 + 0] = __floats2half2_rn(v.x, v.y);
        ((__half2*)g_w1p)[j * 2 + 1] = __floats2half2_rn(v.z, v.w);
        return;
    } else if (i < N4_HA + N4_W1 + N4_W2) {
        j = i - N4_HA - N4_W1; src = w_out; dst = g_w2;
    } else return;
    float4 v = ((const float4*)src)[j];
    ((__half2*)dst)[j * 2 + 0] = __floats2half2_rn(v.x, v.y);
    ((__half2*)dst)[j * 2 + 1] = __floats2half2_rn(v.z, v.w);
}

// ---------------- causal conv + BCx gate, 2 channels/thread (all fp16) ------
#define TPER 8
#define DPAIRS (CONV_DIM / 2)   // 1024

__global__ __launch_bounds__(256)
void conv_gate_kernel(const float* __restrict__ cw)
{
    int dp = blockIdx.x * blockDim.x + threadIdx.x;  // channel pair 0..1023
    int t0 = blockIdx.y * TPER;
    int pos0 = t0 & (SEQ_LEN - 1);

    const __half2* bxp = (const __half2*)g_bxh;
    const __half2* chp = (const __half2*)g_ch;
    __half2* yp = (__half2*)g_y;

    float4 wa = *(const float4*)(cw + dp * 8);       // channel 2*dp
    float4 wb = *(const float4*)(cw + dp * 8 + 4);   // channel 2*dp+1

    float2 h0 = {0.f, 0.f}, h1 = {0.f, 0.f}, h2 = {0.f, 0.f};
    if (pos0 >= 3) h0 = __half22float2(bxp[(size_t)(t0 - 3) * DPAIRS + dp]);
    if (pos0 >= 2) h1 = __half22float2(bxp[(size_t)(t0 - 2) * DPAIRS + dp]);
    if (pos0 >= 1) h2 = __half22float2(bxp[(size_t)(t0 - 1) * DPAIRS + dp]);

#pragma unroll
    for (int i = 0; i < TPER; i++) {
        size_t idx = (size_t)(t0 + i) * DPAIRS + dp;
        float2 bx = __half22float2(bxp[idx]);
        float cx = fmaf(wa.x, h0.x, fmaf(wa.y, h1.x, fmaf(wa.z, h2.x, wa.w * bx.x)));
        float cy = fmaf(wb.x, h0.y, fmaf(wb.y, h1.y, fmaf(wb.z, h2.y, wb.w * bx.y)));
        float2 c = __half22float2(chp[idx]);
        yp[idx] = __floats2half2_rn(c.x * cx, c.y * cy);
        h0 = h1; h1 = h2; h2 = bx;
    }
}

// ---------------- launch -----------------------------------------------------
extern "C" void kernel_launch(void* const* d_in, const int* in_sizes, int n_in,
                              void* d_out, int out_size)
{
    const float* hidden = (const float*)d_in[0];
    const float* w_in   = (const float*)d_in[1];
    const float* convw  = (const float*)d_in[2];
    const float* w_out  = (const float*)d_in[3];
    float* out = (float*)d_out;
    float* states = out + (size_t)NTOK * HIDDEN;

    __half *ha, *w1p, *w2, *y;
    cudaGetSymbolAddress((void**)&ha,  g_ha);
    cudaGetSymbolAddress((void**)&w1p, g_w1p);
    cudaGetSymbolAddress((void**)&w2,  g_w2);
    cudaGetSymbolAddress((void**)&y,   g_y);

    cudaFuncSetAttribute(gemm_f16, cudaFuncAttributeMaxDynamicSharedMemorySize, GSMEM_TOTAL);

    // 0) fused fp16 conversions
    {
        int total = N4_HA + N4_W1 + N4_W2;
        cvt_all_kernel<<<(total + 255) / 256, 256>>>(hidden, w_in, w_out);
    }

    // 1) FUSED in_proj GEMM: bx=b*x fp16 (+fp32 states) AND c-plane fp16
    gemm_f16<<<dim3(BCX_COLS / BN, NTOK / BM), 128, GSMEM_TOTAL>>>(
        ha, w1p, nullptr, CONV_DIM, 1, states);

    // 2) conv + BCx gate -> y (fp16), 2 channels per thread
    conv_gate_kernel<<<dim3(DPAIRS / 256, NTOK / TPER), 256>>>(convw);

    // 3) GEMM2: out = y @ w_out^T
    gemm_f16<<<dim3(HIDDEN / BN, NTOK / BM), 128, GSMEM_TOTAL>>>(
        y, w2, out, HIDDEN, 0, nullptr);
}

// round 17
// speedup vs baseline: 1.0031x; 1.0003x over previous
#include <cuda_runtime.h>
#include <cuda_fp16.h>
#include <stdint.h>

#define NUM_SEQS 4
#define SEQ_LEN  4096
#define NTOK     16384
#define HIDDEN   2048
#define CONV_DIM 2048
#define KSZ      4
#define BCX_COLS 6144
#define KDIM     2048

// ---------------- scratch (static device globals; allocation-free) ----------
__device__ __half g_bxh[(size_t)NTOK * CONV_DIM];    // gated input b*x (fp16)
__device__ __half g_ch[(size_t)NTOK * CONV_DIM];     // c gate (fp16)
__device__ __half g_ha[(size_t)NTOK * KDIM];         // fp16 hidden
__device__ __half g_w1p[(size_t)BCX_COLS * KDIM];    // fp16 w_in, rows permuted:
                                                     //  [0,4096): interleaved b,x ; [4096,6144): c
__device__ __half g_w2[(size_t)HIDDEN * KDIM];       // fp16 w_out
__device__ __half g_y[(size_t)NTOK * KDIM];          // fp16 y

// ---------------- ptx helpers (baseline ISA only) ----------------------------
__device__ __forceinline__ uint32_t smem_u32(const void* p) {
    uint32_t a;
    asm("{ .reg .u64 t; cvta.to.shared.u64 t, %1; cvt.u32.u64 %0, t; }" : "=r"(a) : "l"(p));
    return a;
}
__device__ __forceinline__ void cpasync16(uint32_t dst, const void* src) {
    asm volatile("cp.async.cg.shared.global [%0], [%1], 16;" :: "r"(dst), "l"(src));
}
__device__ __forceinline__ void cp_commit() { asm volatile("cp.async.commit_group;" ::: "memory"); }
__device__ __forceinline__ void cp_wait2()  { asm volatile("cp.async.wait_group 2;" ::: "memory"); }

#define LDSM4(r, addr)                                                      \
    asm volatile("ldmatrix.sync.aligned.m8n8.x4.shared.b16 {%0,%1,%2,%3}, [%4];" \
        : "=r"((r)[0]), "=r"((r)[1]), "=r"((r)[2]), "=r"((r)[3]) : "r"(addr))

#define MMAF16(acc, a, b0r, b1r)                                            \
    asm volatile("mma.sync.aligned.m16n8k16.row.col.f32.f16.f16.f32 "       \
        "{%0,%1,%2,%3}, {%4,%5,%6,%7}, {%8,%9}, {%0,%1,%2,%3};"             \
        : "+f"((acc)[0]), "+f"((acc)[1]), "+f"((acc)[2]), "+f"((acc)[3])    \
        : "r"((a)[0]), "r"((a)[1]), "r"((a)[2]), "r"((a)[3]),               \
          "r"(b0r), "r"(b1r))

__device__ __forceinline__ uint32_t swz64(uint32_t off) { return off ^ ((off >> 3) & 0x30); }

// ---------------- fp16 GEMM: C = A[M,K] @ B[N,K]^T --------------------------
// CTA 128x128, 4 warps (2x2), warp tile 64x64, BK=32 halves, 4-stage,
// double-buffered register fragments, 2 CTAs/SM.
// mode 0: plain fp32 C
// mode 1: FUSED in_proj: n0 < 4096 -> interleaved (b,x) -> bx fp16 (g_bxh)
//                        + fp32 states; n0 >= 4096 -> c plane fp16 (g_ch).
#define BM 128
#define BN 128
#define BKC 32
#define NC (KDIM / BKC)              // 64
#define OFF_A 0
#define OFF_B 8192
#define STAGE_BYTES 16384
#define GSMEM_TOTAL (4 * STAGE_BYTES)   // 64KB

__global__ __launch_bounds__(128, 2)
void gemm_f16(const __half* __restrict__ A, const __half* __restrict__ B,
              float* __restrict__ C, int ldC, int mode, float* __restrict__ states)
{
    extern __shared__ char smem[];
    const uint32_t sbase = smem_u32(smem);
    const int tid  = threadIdx.x;
    const int lane = tid & 31;
    const int wid  = tid >> 5;
    const int wm   = wid >> 1;
    const int wn   = wid & 1;
    const int m0 = blockIdx.y * BM;
    const int n0 = blockIdx.x * BN;

    const __half* gA = A + (size_t)m0 * KDIM;
    const __half* gB = B + (size_t)n0 * KDIM;

    uint32_t aRow[4], aXor[4];
#pragma unroll
    for (int mt = 0; mt < 4; mt++) {
        uint32_t r = wm * 64 + mt * 16 + (lane & 15);
        aRow[mt] = r * 64;
        aXor[mt] = (aRow[mt] >> 3) & 0x30;
    }
    const uint32_t aS = (lane >> 4);
    uint32_t bRow[4], bXor[4];
#pragma unroll
    for (int p = 0; p < 4; p++) {
        uint32_t r = wn * 64 + p * 16 + (lane & 7) + ((lane >> 4) << 3);
        bRow[p] = r * 64;
        bXor[p] = (bRow[p] >> 3) & 0x30;
    }
    const uint32_t bS = ((lane >> 3) & 1);

    float acc[4][8][4];
#pragma unroll
    for (int i = 0; i < 4; i++)
#pragma unroll
        for (int j = 0; j < 8; j++)
#pragma unroll
            for (int q = 0; q < 4; q++) acc[i][j][q] = 0.0f;

    auto load_chunk = [&](int c, int st) {
        const uint32_t stg = sbase + st * STAGE_BYTES;
        const int koff = c * BKC;
#pragma unroll
        for (int p = 0; p < 4; p++) {
            int u = p * 128 + tid;
            int r = u >> 2, s = u & 3;
            cpasync16(stg + OFF_A + swz64((uint32_t)(r * 64 + s * 16)),
                      gA + (size_t)r * KDIM + koff + s * 8);
        }
#pragma unroll
        for (int p = 0; p < 4; p++) {
            int u = p * 128 + tid;
            int r = u >> 2, s = u & 3;
            cpasync16(stg + OFF_B + swz64((uint32_t)(r * 64 + s * 16)),
                      gB + (size_t)r * KDIM + koff + s * 8);
        }
    };

    uint32_t af0[4][4], bf0[4][4], af1[4][4], bf1[4][4];

    auto ldsm_set = [&](uint32_t stg, int q, uint32_t af[4][4], uint32_t bf[4][4]) {
        const uint32_t s_a = (q * 2 + aS) * 16;
        const uint32_t s_b = (q * 2 + bS) * 16;
#pragma unroll
        for (int mt = 0; mt < 4; mt++)
            LDSM4(af[mt], stg + OFF_A + aRow[mt] + (s_a ^ aXor[mt]));
#pragma unroll
        for (int p = 0; p < 4; p++)
            LDSM4(bf[p], stg + OFF_B + bRow[p] + (s_b ^ bXor[p]));
    };

    auto mma_set = [&](uint32_t af[4][4], uint32_t bf[4][4]) {
#pragma unroll
        for (int mt = 0; mt < 4; mt++) {
#pragma unroll
            for (int nt = 0; nt < 8; nt++) {
                const int p = nt >> 1, bi = (nt & 1) * 2;
                MMAF16(acc[mt][nt], af[mt], bf[p][bi], bf[p][bi + 1]);
            }
        }
    };

    // prologue: stages 0,1,2
    load_chunk(0, 0); cp_commit();
    load_chunk(1, 1); cp_commit();
    load_chunk(2, 2); cp_commit();
    cp_wait2();
    __syncthreads();
    ldsm_set(sbase, 0, af0, bf0);

    for (int ch = 0; ch < NC; ch++) {
        const uint32_t stg = sbase + (ch & 3) * STAGE_BYTES;
        if (ch + 3 < NC) load_chunk(ch + 3, (ch + 3) & 3);
        cp_commit();

        ldsm_set(stg, 1, af1, bf1);
        mma_set(af0, bf0);
        mma_set(af1, bf1);

        cp_wait2();
        __syncthreads();
        if (ch + 1 < NC)
            ldsm_set(sbase + ((ch + 1) & 3) * STAGE_BYTES, 0, af0, bf0);
    }

    if (mode == 0) {
        const int rw = m0 + wm * 64 + (lane >> 2);
        const int cw = n0 + wn * 64 + (lane & 3) * 2;
#pragma unroll
        for (int mt = 0; mt < 4; mt++) {
#pragma unroll
            for (int nt = 0; nt < 8; nt++) {
                float* p0 = C + (size_t)(rw + mt * 16) * ldC + cw + nt * 8;
                float* p1 = C + (size_t)(rw + mt * 16 + 8) * ldC + cw + nt * 8;
                *(float2*)p0 = make_float2(acc[mt][nt][0], acc[mt][nt][1]);
                *(float2*)p1 = make_float2(acc[mt][nt][2], acc[mt][nt][3]);
            }
        }
    } else if (n0 < 4096) {
        // interleaved (b,x): acc cols (2i, 2i+1) = (b_i, x_i); bx col = i
        const int rw0  = m0 + wm * 64 + (lane >> 2);
        const int colb = (n0 >> 1) + wn * 32 + (lane & 3);
#pragma unroll
        for (int mt = 0; mt < 4; mt++) {
#pragma unroll
            for (int nt = 0; nt < 8; nt++) {
                int col = colb + nt * 4;
                int r0 = rw0 + mt * 16;
                int r1 = r0 + 8;
                float p0 = acc[mt][nt][0] * acc[mt][nt][1];
                float p1 = acc[mt][nt][2] * acc[mt][nt][3];
                g_bxh[(size_t)r0 * CONV_DIM + col] = __float2half_rn(p0);
                g_bxh[(size_t)r1 * CONV_DIM + col] = __float2half_rn(p1);
                int pos0 = r0 & (SEQ_LEN - 1);
                if (pos0 >= SEQ_LEN - (KSZ - 1))
                    states[((size_t)(r0 >> 12) * (KSZ - 1) + (pos0 - (SEQ_LEN - 3))) * CONV_DIM + col] = p0;
                int pos1 = r1 & (SEQ_LEN - 1);
                if (pos1 >= SEQ_LEN - (KSZ - 1))
                    states[((size_t)(r1 >> 12) * (KSZ - 1) + (pos1 - (SEQ_LEN - 3))) * CONV_DIM + col] = p1;
            }
        }
    } else {
        // c plane -> fp16 g_ch, col = n0 - 4096
        const int rw = m0 + wm * 64 + (lane >> 2);
        const int cw = (n0 - 4096) + wn * 64 + (lane & 3) * 2;
#pragma unroll
        for (int mt = 0; mt < 4; mt++) {
#pragma unroll
            for (int nt = 0; nt < 8; nt++) {
                __half2* p0 = (__half2*)&g_ch[(size_t)(rw + mt * 16) * CONV_DIM + cw + nt * 8];
                __half2* p1 = (__half2*)&g_ch[(size_t)(rw + mt * 16 + 8) * CONV_DIM + cw + nt * 8];
                *p0 = __floats2half2_rn(acc[mt][nt][0], acc[mt][nt][1]);
                *p1 = __floats2half2_rn(acc[mt][nt][2], acc[mt][nt][3]);
            }
        }
    }
}

// ---------------- fused fp32 -> fp16 converts (hidden | w_in permuted | w_out)
#define N4_HA (NTOK * KDIM / 4)
#define N4_W1 (BCX_COLS * KDIM / 4)
#define N4_W2 (HIDDEN * KDIM / 4)

__global__ __launch_bounds__(256)
void cvt_all_kernel(const float* __restrict__ hidden, const float* __restrict__ w_in,
                    const float* __restrict__ w_out)
{
    int i = blockIdx.x * blockDim.x + threadIdx.x;
    const float* src;
    __half* dst;
    int j;
    if (i < N4_HA) {
        j = i; src = hidden; dst = g_ha;
    } else if (i < N4_HA + N4_W1) {
        j = i - N4_HA;
        int r = (j * 4) / KDIM, k = (j * 4) % KDIM;
        int sr = (r < 4096) ? ((r >> 1) + ((r & 1) ? 4096 : 0)) : (r - 2048);
        float4 v = *(const float4*)(w_in + (size_t)sr * KDIM + k);
        ((__half2*)g_w1p)[j * 2 + 0] = __floats2half2_rn(v.x, v.y);
        ((__half2*)g_w1p)[j * 2 + 1] = __floats2half2_rn(v.z, v.w);
        return;
    } else if (i < N4_HA + N4_W1 + N4_W2) {
        j = i - N4_HA - N4_W1; src = w_out; dst = g_w2;
    } else return;
    float4 v = ((const float4*)src)[j];
    ((__half2*)dst)[j * 2 + 0] = __floats2half2_rn(v.x, v.y);
    ((__half2*)dst)[j * 2 + 1] = __floats2half2_rn(v.z, v.w);
}

// ---------------- causal conv + BCx gate, 2 channels/thread (all fp16) ------
#define TPER 8
#define DPAIRS (CONV_DIM / 2)   // 1024

__global__ __launch_bounds__(256)
void conv_gate_kernel(const float* __restrict__ cw)
{
    int dp = blockIdx.x * blockDim.x + threadIdx.x;  // channel pair 0..1023
    int t0 = blockIdx.y * TPER;
    int pos0 = t0 & (SEQ_LEN - 1);

    const __half2* bxp = (const __half2*)g_bxh;
    const __half2* chp = (const __half2*)g_ch;
    __half2* yp = (__half2*)g_y;

    float4 wa = *(const float4*)(cw + dp * 8);       // channel 2*dp
    float4 wb = *(const float4*)(cw + dp * 8 + 4);   // channel 2*dp+1

    float2 h0 = {0.f, 0.f}, h1 = {0.f, 0.f}, h2 = {0.f, 0.f};
    if (pos0 >= 3) h0 = __half22float2(bxp[(size_t)(t0 - 3) * DPAIRS + dp]);
    if (pos0 >= 2) h1 = __half22float2(bxp[(size_t)(t0 - 2) * DPAIRS + dp]);
    if (pos0 >= 1) h2 = __half22float2(bxp[(size_t)(t0 - 1) * DPAIRS + dp]);

#pragma unroll
    for (int i = 0; i < TPER; i++) {
        size_t idx = (size_t)(t0 + i) * DPAIRS + dp;
        float2 bx = __half22float2(bxp[idx]);
        float cx = fmaf(wa.x, h0.x, fmaf(wa.y, h1.x, fmaf(wa.z, h2.x, wa.w * bx.x)));
        float cy = fmaf(wb.x, h0.y, fmaf(wb.y, h1.y, fmaf(wb.z, h2.y, wb.w * bx.y)));
        float2 c = __half22float2(chp[idx]);
        yp[idx] = __floats2half2_rn(c.x * cx, c.y * cy);
        h0 = h1; h1 = h2; h2 = bx;
    }
}

// ---------------- launch -----------------------------------------------------
extern "C" void kernel_launch(void* const* d_in, const int* in_sizes, int n_in,
                              void* d_out, int out_size)
{
    const float* hidden = (const float*)d_in[0];
    const float* w_in   = (const float*)d_in[1];
    const float* convw  = (const float*)d_in[2];
    const float* w_out  = (const float*)d_in[3];
    float* out = (float*)d_out;
    float* states = out + (size_t)NTOK * HIDDEN;

    __half *ha, *w1p, *w2, *y;
    cudaGetSymbolAddress((void**)&ha,  g_ha);
    cudaGetSymbolAddress((void**)&w1p, g_w1p);
    cudaGetSymbolAddress((void**)&w2,  g_w2);
    cudaGetSymbolAddress((void**)&y,   g_y);

    cudaFuncSetAttribute(gemm_f16, cudaFuncAttributeMaxDynamicSharedMemorySize, GSMEM_TOTAL);

    // 0) fused fp16 conversions
    {
        int total = N4_HA + N4_W1 + N4_W2;
        cvt_all_kernel<<<(total + 255) / 256, 256>>>(hidden, w_in, w_out);
    }

    // 1) FUSED in_proj GEMM: bx=b*x fp16 (+fp32 states) AND c-plane fp16
    gemm_f16<<<dim3(BCX_COLS / BN, NTOK / BM), 128, GSMEM_TOTAL>>>(
        ha, w1p, nullptr, CONV_DIM, 1, states);

    // 2) conv + BCx gate -> y (fp16), 2 channels per thread
    conv_gate_kernel<<<dim3(DPAIRS / 256, NTOK / TPER), 256>>>(convw);

    // 3) GEMM2: out = y @ w_out^T
    gemm_f16<<<dim3(HIDDEN / BN, NTOK / BM), 128, GSMEM_TOTAL>>>(
        y, w2, out, HIDDEN, 0, nullptr);
}